// round 15
// baseline (speedup 1.0000x reference)
#include <cuda_runtime.h>
#include <cuda_fp16.h>
#include <math.h>
#include <stdint.h>

#define Bsz   2048
#define Ssz   23
#define Esz   768
#define REDsz 256
#define Hsz   8
#define DHsz  32
#define NLAB  25
#define Mrows (Bsz*Ssz)     // 47104
#define MCtiles 369
#define MCc   (MCtiles*128) // 47232

// GEMM pipeline config: fp16, BM=128, BN=64, BK=32, 4 stages, 3 CTAs/SM
#define STAGES    4
#define ROWB      80
#define ATILE_B   (128*ROWB)            // 10240
#define BTILE_B   (64*ROWB)             // 5120
#define STAGE_B   (ATILE_B + BTILE_B)   // 15360
#define SMEM_DYN  (STAGES*STAGE_B)      // 61440

// fp16 weight scratch offsets (halves)
#define W1N  (384*768)
#define W2N  (256*384)
#define WQN  (256*256)
#define OFF_W1 0
#define OFF_W2 (OFF_W1 + W1N)
#define OFF_WQ (OFF_W2 + W2N)
#define OFF_WK (OFF_WQ + WQN)
#define OFF_WV (OFF_WK + WQN)
#define OFF_WO (OFF_WV + WQN)
#define WTOT   (OFF_WO + WQN)

// ---------------- scratch (allocation-free; zero-initialized) ----------------
__device__ __half g_ac   [(size_t)MCc*768];
__device__ __half g_h1c  [(size_t)MCc*384];
__device__ float  g_h2c  [(size_t)MCc*256];
__device__ float  g_redc [(size_t)MCc*256];
__device__ __half g_redch[(size_t)MCc*256];
__device__ float  g_qc   [(size_t)MCc*256];
__device__ float  g_kc   [(size_t)MCc*256];
__device__ float  g_vc   [(size_t)MCc*256];
__device__ __half g_ctxc [(size_t)MCc*256];
__device__ float  g_updc [(size_t)MCc*256];
__device__ __half g_wh   [WTOT];
__device__ int    g_r2c  [Mrows];
__device__ int    g_m2c  [Mrows];
__device__ int    g_any  [Bsz];
__device__ int    g_cnt;
__device__ int    g_mcnt;
__device__ unsigned char g_use[Mrows];
__device__ float  g_acc;

__device__ __forceinline__ float gelu_f(float x) {
    return 0.5f * x * (1.0f + erff(x * 0.70710678118654752440f));
}

__device__ __forceinline__ uint32_t smem_u32(const void* p) {
    uint32_t a;
    asm("{ .reg .u64 t; cvta.to.shared.u64 t, %1; cvt.u32.u64 %0, t; }" : "=r"(a) : "l"(p));
    return a;
}

__device__ __forceinline__ void mma_f16(float* d, const uint32_t* a, const uint32_t* b) {
    asm volatile(
        "mma.sync.aligned.m16n8k16.row.col.f32.f16.f16.f32 "
        "{%0,%1,%2,%3}, {%4,%5,%6,%7}, {%8,%9}, {%0,%1,%2,%3};"
        : "+f"(d[0]), "+f"(d[1]), "+f"(d[2]), "+f"(d[3])
        : "r"(a[0]), "r"(a[1]), "r"(a[2]), "r"(a[3]), "r"(b[0]), "r"(b[1]));
}

#define LDSM_X4(r0_, r1_, r2_, r3_, addr_) \
    asm volatile("ldmatrix.sync.aligned.m8n8.x4.shared.b16 {%0,%1,%2,%3}, [%4];" \
                 : "=r"(r0_), "=r"(r1_), "=r"(r2_), "=r"(r3_) : "r"(addr_))
#define LDSM_X2(r0_, r1_, addr_) \
    asm volatile("ldmatrix.sync.aligned.m8n8.x2.shared.b16 {%0,%1}, [%2];" \
                 : "=r"(r0_), "=r"(r1_) : "r"(addr_))

#define CP_ASYNC16(dst_, src_) \
    asm volatile("cp.async.cg.shared.global [%0], [%1], 16;" :: "r"(dst_), "l"(src_) : "memory")
#define CP_COMMIT() asm volatile("cp.async.commit_group;" ::: "memory")
#define CP_WAIT(n_)  asm volatile("cp.async.wait_group %0;" :: "n"(n_) : "memory")

// ---------------- prep ----------------
__global__ void prep_k(const int* __restrict__ mask)
{
    int b = blockIdx.x * 256 + threadIdx.x;
    if (b == 0) { g_cnt = Ssz; g_mcnt = 0; }
    if (b >= Bsz) return;
    int a = 0;
    #pragma unroll
    for (int s = 0; s < Ssz; s++) a |= (mask[b * Ssz + s] > 0);
    g_any[b] = a;
}

__global__ void assign_k(const int* __restrict__ mask)
{
    int r = blockIdx.x * 256 + threadIdx.x;
    if (r >= Mrows) return;
    int exist = mask[r] > 0;
    if (exist) g_r2c[r] = atomicAdd(&g_cnt, 1);
    else       g_r2c[r] = r % Ssz;
    int use = (!exist) && g_any[r / Ssz];
    g_use[r] = (unsigned char)use;
    if (use) g_m2c[r] = atomicAdd(&g_mcnt, 1);
}

__global__ void acopy_k(const float* __restrict__ cls, const float* __restrict__ miss,
                        const int* __restrict__ mask)
{
    int idx = blockIdx.x * 256 + threadIdx.x;
    const int CH = Esz / 8;
    if (idx >= (Mrows + Ssz) * CH) return;
    const float* src; int drow, c;
    if (idx < Ssz * CH) {
        int s = idx / CH; c = (idx - s * CH) * 8;
        src = miss + (size_t)s * Esz + c; drow = s;
    } else {
        int j = idx - Ssz * CH;
        int r = j / CH; c = (j - r * CH) * 8;
        if (mask[r] <= 0) return;
        src = cls + (size_t)r * Esz + c; drow = g_r2c[r];
    }
    float4 v0 = *reinterpret_cast<const float4*>(src);
    float4 v1 = *reinterpret_cast<const float4*>(src + 4);
    __half2 h0 = __floats2half2_rn(v0.x, v0.y);
    __half2 h1 = __floats2half2_rn(v0.z, v0.w);
    __half2 h2 = __floats2half2_rn(v1.x, v1.y);
    __half2 h3 = __floats2half2_rn(v1.z, v1.w);
    uint4 o;
    o.x = *reinterpret_cast<uint32_t*>(&h0);
    o.y = *reinterpret_cast<uint32_t*>(&h1);
    o.z = *reinterpret_cast<uint32_t*>(&h2);
    o.w = *reinterpret_cast<uint32_t*>(&h3);
    *reinterpret_cast<uint4*>(&g_ac[(size_t)drow * Esz + c]) = o;
}

__global__ void wprep_k(const float* __restrict__ W1, const float* __restrict__ W2,
                        const float* __restrict__ Wq, const float* __restrict__ Wk,
                        const float* __restrict__ Wv, const float* __restrict__ Wo)
{
    int i = blockIdx.x * 256 + threadIdx.x;
    if (i >= WTOT) return;
    float v;
    if      (i < OFF_W2) v = W1[i - OFF_W1];
    else if (i < OFF_WQ) v = W2[i - OFF_W2];
    else if (i < OFF_WK) v = Wq[i - OFF_WQ];
    else if (i < OFF_WV) v = Wk[i - OFF_WK];
    else if (i < OFF_WO) v = Wv[i - OFF_WV];
    else                 v = Wo[i - OFF_WO];
    g_wh[i] = __float2half_rn(v);
}

// ---------------- HMMA fp16 GEMM: BM=128, BN=64, BK=32, warp tile 32x32 ----------------
// 8 warps: wm = wid&3 (32 rows), wn = wid>>2 (32 cols). 3 CTAs/SM.
// GUARD: 0 none, 1 exit if bm>=g_cnt, 2 exit if bm>=g_mcnt.
// MODE 0: plain. MODE 3: fused QKV (grid.x = 12; q-branch only tile bm==0).
template<int ACT, int MODE, int OUTH, int GUARD>
__global__ void __launch_bounds__(256, 3) mmagemm_k(
    const __half* __restrict__ A,
    const __half* __restrict__ Wa, const __half* __restrict__ Wb, const __half* __restrict__ Wc,
    const float* __restrict__ ba, const float* __restrict__ bb, const float* __restrict__ bc,
    void* __restrict__ Cav, void* __restrict__ Cbv, void* __restrict__ Ccv,
    int N, int K)
{
    extern __shared__ char dynS[];

    const int bm = blockIdx.y * 128;
    if (GUARD == 1) { if (bm >= g_cnt)  return; }
    if (GUARD == 2) { if (bm >= g_mcnt) return; }

    const int tid  = threadIdx.x;
    const int lane = tid & 31;
    const int wid  = tid >> 5;
    const int g    = lane >> 2;
    const int tg   = lane & 3;
    const int wm   = wid & 3;      // m block of 32 rows
    const int wn   = wid >> 2;     // n block of 32 cols

    const __half* W; const float* bias; void* Cv; int bn;
    if (MODE == 3) {
        int sel = blockIdx.x >> 2;
        if (sel == 0 && bm > 0) return;     // q needed only for miss rows 0..22
        W    = sel == 0 ? Wa : sel == 1 ? Wb : Wc;
        bias = sel == 0 ? ba : sel == 1 ? bb : bc;
        Cv   = sel == 0 ? Cav : sel == 1 ? Cbv : Ccv;
        bn = (blockIdx.x & 3) * 64;
    } else {
        W = Wa; bias = ba; Cv = Cav;
        bn = blockIdx.x * 64;
    }

    const uint32_t sBase = smem_u32(dynS);

    // ldmatrix per-lane bases (within a stage)
    const int lr = lane & 7;
    const int li = lane >> 3;
    const uint32_t aLd = sBase +
        (uint32_t)((wm * 32 + (li & 1) * 8 + lr) * ROWB + (li >> 1) * 16);
    const uint32_t bLd = sBase + ATILE_B +
        (uint32_t)((wn * 32 + lr) * ROWB + (li & 1) * 16);

    // staging: A row tid>>1 (2 chunks), B row tid>>2 (1 chunk)
    const int arow = tid >> 1;
    const int ah   = (tid & 1) * 16;          // halves
    const int brow = tid >> 2;
    const int bq4  = (tid & 3) * 8;           // halves
    const uint32_t aSt = sBase + (uint32_t)(arow * ROWB + (tid & 1) * 32);
    const uint32_t bSt = sBase + ATILE_B + (uint32_t)(brow * ROWB + (tid & 3) * 16);

    const __half* Arow = A + (size_t)(bm + arow) * K;
    const __half* Brow = W + (size_t)(bn + brow) * K;

    const int nT = K >> 5;

    #pragma unroll
    for (int t = 0; t < STAGES - 1; t++) {
        uint32_t so = (uint32_t)(t * STAGE_B);
        const __half* as = Arow + t * 32 + ah;
        CP_ASYNC16(aSt + so,      as);
        CP_ASYNC16(aSt + so + 16, as + 8);
        CP_ASYNC16(bSt + so, Brow + t * 32 + bq4);
        CP_COMMIT();
    }

    float acc[2][4][4] = {};
    int cs = 0, is = STAGES - 1;

    for (int t = 0; t < nT; t++) {
        CP_WAIT(STAGES - 2);
        __syncthreads();

        int ft = t + STAGES - 1;
        if (ft < nT) {
            uint32_t so = (uint32_t)(is * STAGE_B);
            const __half* as = Arow + ft * 32 + ah;
            CP_ASYNC16(aSt + so,      as);
            CP_ASYNC16(aSt + so + 16, as + 8);
            CP_ASYNC16(bSt + so, Brow + ft * 32 + bq4);
        }
        CP_COMMIT();
        if (++is == STAGES) is = 0;

        const uint32_t so = (uint32_t)(cs * STAGE_B);
        #pragma unroll
        for (int ks = 0; ks < 2; ks++) {
            const uint32_t kOff = so + (uint32_t)(ks * 32);
            uint32_t af[2][4];
            #pragma unroll
            for (int mt = 0; mt < 2; mt++)
                LDSM_X4(af[mt][0], af[mt][1], af[mt][2], af[mt][3],
                        aLd + (uint32_t)(mt * 16 * ROWB) + kOff);
            uint32_t bf[4][2];
            #pragma unroll
            for (int nt = 0; nt < 4; nt++)
                LDSM_X2(bf[nt][0], bf[nt][1],
                        bLd + (uint32_t)(nt * 8 * ROWB) + kOff);
            #pragma unroll
            for (int mt = 0; mt < 2; mt++)
                #pragma unroll
                for (int nt = 0; nt < 4; nt++)
                    mma_f16(acc[mt][nt], af[mt], bf[nt]);
        }
        if (++cs == STAGES) cs = 0;
    }

    #pragma unroll
    for (int mt = 0; mt < 2; mt++) {
        int m0 = bm + wm * 32 + mt * 16 + g;
        int m1 = m0 + 8;
        #pragma unroll
        for (int nt = 0; nt < 4; nt++) {
            int n = bn + wn * 32 + nt * 8 + 2 * tg;
            float2 bz = *reinterpret_cast<const float2*>(bias + n);
            float2 o0, o1;
            o0.x = acc[mt][nt][0] + bz.x; o0.y = acc[mt][nt][1] + bz.y;
            o1.x = acc[mt][nt][2] + bz.x; o1.y = acc[mt][nt][3] + bz.y;
            if (ACT == 1) {
                o0.x = gelu_f(o0.x); o0.y = gelu_f(o0.y);
                o1.x = gelu_f(o1.x); o1.y = gelu_f(o1.y);
            }
            if (OUTH) {
                __half* Ch = (__half*)Cv;
                __half2 h0 = __floats2half2_rn(o0.x, o0.y);
                __half2 h1 = __floats2half2_rn(o1.x, o1.y);
                *reinterpret_cast<__half2*>(&Ch[(size_t)m0 * N + n]) = h0;
                *reinterpret_cast<__half2*>(&Ch[(size_t)m1 * N + n]) = h1;
            } else {
                float* C = (float*)Cv;
                *reinterpret_cast<float2*>(&C[(size_t)m0 * N + n]) = o0;
                *reinterpret_cast<float2*>(&C[(size_t)m1 * N + n]) = o1;
            }
        }
    }
}

// ---------------- LayerNorm (compacted): one WARP per row ----------------
__global__ void ln_k(const float* __restrict__ gam, const float* __restrict__ bet)
{
    const int wid = threadIdx.x >> 5, lane = threadIdx.x & 31;
    const int r = blockIdx.x * 8 + wid;
    if (r >= g_cnt) return;
    const float* x = &g_h2c[(size_t)r * 256 + lane * 8];
    float4 v0 = *reinterpret_cast<const float4*>(x);
    float4 v1 = *reinterpret_cast<const float4*>(x + 4);
    float s = v0.x+v0.y+v0.z+v0.w + v1.x+v1.y+v1.z+v1.w;
    #pragma unroll
    for (int o = 16; o > 0; o >>= 1) s += __shfl_xor_sync(0xffffffffu, s, o);
    float mu = s * (1.0f / 256.0f);
    float d0x=v0.x-mu, d0y=v0.y-mu, d0z=v0.z-mu, d0w=v0.w-mu;
    float d1x=v1.x-mu, d1y=v1.y-mu, d1z=v1.z-mu, d1w=v1.w-mu;
    float sq = d0x*d0x+d0y*d0y+d0z*d0z+d0w*d0w + d1x*d1x+d1y*d1y+d1z*d1z+d1w*d1w;
    #pragma unroll
    for (int o = 16; o > 0; o >>= 1) sq += __shfl_xor_sync(0xffffffffu, sq, o);
    float rs = rsqrtf(sq * (1.0f / 256.0f) + 1e-5f);
    float4 ga0 = *reinterpret_cast<const float4*>(gam + lane * 8);
    float4 ga1 = *reinterpret_cast<const float4*>(gam + lane * 8 + 4);
    float4 be0 = *reinterpret_cast<const float4*>(bet + lane * 8);
    float4 be1 = *reinterpret_cast<const float4*>(bet + lane * 8 + 4);
    float4 o0, o1;
    o0.x = d0x*rs*ga0.x + be0.x; o0.y = d0y*rs*ga0.y + be0.y;
    o0.z = d0z*rs*ga0.z + be0.z; o0.w = d0w*rs*ga0.w + be0.w;
    o1.x = d1x*rs*ga1.x + be1.x; o1.y = d1y*rs*ga1.y + be1.y;
    o1.z = d1z*rs*ga1.z + be1.z; o1.w = d1w*rs*ga1.w + be1.w;
    float* y = &g_redc[(size_t)r * 256 + lane * 8];
    *reinterpret_cast<float4*>(y)     = o0;
    *reinterpret_cast<float4*>(y + 4) = o1;
    __half2 h0 = __floats2half2_rn(o0.x, o0.y);
    __half2 h1 = __floats2half2_rn(o0.z, o0.w);
    __half2 h2 = __floats2half2_rn(o1.x, o1.y);
    __half2 h3 = __floats2half2_rn(o1.z, o1.w);
    uint4 hv;
    hv.x = *reinterpret_cast<uint32_t*>(&h0);
    hv.y = *reinterpret_cast<uint32_t*>(&h1);
    hv.z = *reinterpret_cast<uint32_t*>(&h2);
    hv.w = *reinterpret_cast<uint32_t*>(&h3);
    *reinterpret_cast<uint4*>(&g_redch[(size_t)r * 256 + lane * 8]) = hv;
}

// ---------------- attention: block per batch, warp per head, only use-rows ----------------
__global__ void attn_k(const int* __restrict__ mask)
{
    int b = blockIdx.x, tid = threadIdx.x;
    int h = tid >> 5, lane = tid & 31;
    __shared__ float qs[Hsz][Ssz][33], ks[Hsz][Ssz][33], vs[Hsz][Ssz][33];
    __shared__ float sc[Hsz][Ssz][Ssz + 1];
    __shared__ int exS[Ssz], useS[Ssz], idxS[Ssz], midS[Ssz];

    if (b == 0 && tid == 0) g_acc = 0.0f;
    if (tid < Ssz) {
        int r = b * Ssz + tid;
        exS[tid]  = (mask[r] > 0);
        useS[tid] = g_use[r];
        idxS[tid] = g_r2c[r];
        midS[tid] = g_use[r] ? g_m2c[r] : 0;
    }
    __syncthreads();
    if (!g_any[b]) return;

    #pragma unroll
    for (int s = 0; s < Ssz; s++) {
        size_t base = (size_t)idxS[s] * REDsz + h * DHsz + lane;
        if (exS[s]) {                    // masked keys never contribute
            ks[h][s][lane] = g_kc[base];
            vs[h][s][lane] = g_vc[base];
        } else {
            vs[h][s][lane] = 0.0f;       // weight is exactly 0; avoid garbage*0
        }
        if (useS[s]) qs[h][s][lane] = g_qc[base];
    }
    __syncwarp();

    for (int idx = lane; idx < Ssz * Ssz; idx += 32) {
        int i = idx / Ssz, j = idx - i * Ssz;
        if (!useS[i]) continue;
        if (exS[j]) {
            float dot = 0.0f;
            #pragma unroll
            for (int d = 0; d < 32; d++) dot += qs[h][i][d] * ks[h][j][d];
            sc[h][i][j] = dot * 0.17677669529663687f;
        } else {
            sc[h][i][j] = -1e9f;
        }
    }
    __syncwarp();

    if (lane < Ssz && useS[lane]) {
        int i = lane;
        float m = -1e30f;
        #pragma unroll
        for (int j = 0; j < Ssz; j++) m = fmaxf(m, sc[h][i][j]);
        float sum = 0.0f;
        #pragma unroll
        for (int j = 0; j < Ssz; j++) { float e = expf(sc[h][i][j] - m); sc[h][i][j] = e; sum += e; }
        float inv = 1.0f / sum;
        #pragma unroll
        for (int j = 0; j < Ssz; j++) sc[h][i][j] *= inv;
    }
    __syncwarp();

    #pragma unroll
    for (int i = 0; i < Ssz; i++) {
        if (!useS[i]) continue;
        float s = 0.0f;
        #pragma unroll
        for (int j = 0; j < Ssz; j++) s += sc[h][i][j] * vs[h][j][lane];
        g_ctxc[(size_t)midS[i] * REDsz + h * DHsz + lane] = __float2half_rn(s);
    }
}

// ---------------- merged orthogonality loss + logits (float4 dots) ----------------
__global__ void losslogit_k(const float* __restrict__ Wp, const float* __restrict__ bp,
                            float* __restrict__ out, int loff)
{
    int b = blockIdx.x, tid = threadIdx.x;
    __shared__ __align__(16) float X[Ssz][260];
    __shared__ float inv[Ssz];
    __shared__ float mean[REDsz];
    __shared__ const float* srcS[Ssz];
    if (tid < Ssz) {
        int r = b * Ssz + tid;
        srcS[tid] = g_use[r] ? &g_updc[(size_t)g_m2c[r] * 256]
                             : &g_redc[(size_t)g_r2c[r] * 256];
    }
    __syncthreads();
    for (int idx = tid; idx < Ssz * REDsz; idx += 256) {
        int s = idx >> 8, d = idx & 255;
        X[s][d] = srcS[s][d];
    }
    __syncthreads();
    int w = tid >> 5, lane = tid & 31;
    for (int r = w; r < Ssz; r += 8) {
        float s = 0.0f;
        for (int d = lane; d < 256; d += 32) s += X[r][d] * X[r][d];
        for (int o = 16; o > 0; o >>= 1) s += __shfl_down_sync(0xffffffffu, s, o);
        if (lane == 0) inv[r] = 1.0f / fmaxf(sqrtf(s), 1e-8f);
    }
    {
        float s = 0.0f;
        #pragma unroll
        for (int ss = 0; ss < Ssz; ss++) s += X[ss][tid];
        mean[tid] = s * (1.0f / (float)Ssz);
    }
    __syncthreads();
    float part = 0.0f;
    if (tid < (Ssz * (Ssz - 1)) / 2) {
        int p = tid, i = 0;
        while (p >= Ssz - 1 - i) { p -= Ssz - 1 - i; i++; }
        int j = i + 1 + p;
        const float4* xi = reinterpret_cast<const float4*>(&X[i][0]);
        const float4* xj = reinterpret_cast<const float4*>(&X[j][0]);
        float dot = 0.0f;
        #pragma unroll 8
        for (int d = 0; d < 64; d++) {
            float4 a = xi[d], c = xj[d];
            dot += a.x*c.x + a.y*c.y + a.z*c.z + a.w*c.w;
        }
        float gv = fabsf(dot * inv[i] * inv[j]);
        part = fmaxf(gv - 0.1f, 0.0f) * 2.0f;
    }
    __shared__ float red[256];
    red[tid] = part; __syncthreads();
    for (int s = 128; s > 0; s >>= 1) { if (tid < s) red[tid] += red[tid + s]; __syncthreads(); }
    if (tid == 0) atomicAdd(&g_acc, red[0]);
    if (tid < NLAB) {
        float a = bp[tid];
        const float* wr = Wp + tid * REDsz;
        for (int d = 0; d < REDsz; d++) a += mean[d] * wr[d];
        out[loff + b * NLAB + tid] = a;
    }
}

__global__ void fin_k(float* out, int writeloss)
{
    if (writeloss)
        out[0] = g_acc * (1.0f / ((float)Bsz * Ssz * (Ssz - 1)));
}

// ---------------- launch ----------------
extern "C" void kernel_launch(void* const* d_in, const int* in_sizes, int n_in,
                              void* d_out, int out_size)
{
    const float* cls  = (const float*)d_in[0];
    const int*   mask = (const int*)  d_in[1];
    const float* miss = (const float*)d_in[2];
    const float* W1 = (const float*)d_in[3];  const float* b1 = (const float*)d_in[4];
    const float* W2 = (const float*)d_in[5];  const float* b2 = (const float*)d_in[6];
    const float* lg = (const float*)d_in[7];  const float* lb = (const float*)d_in[8];
    const float* Wq = (const float*)d_in[9];  const float* bq = (const float*)d_in[10];
    const float* Wk = (const float*)d_in[11]; const float* bk = (const float*)d_in[12];
    const float* Wv = (const float*)d_in[13]; const float* bv = (const float*)d_in[14];
    const float* Wo = (const float*)d_in[15]; const float* bo = (const float*)d_in[16];
    const float* Wp = (const float*)d_in[17]; const float* bp = (const float*)d_in[18];
    float* out = (float*)d_out;

    int loff = out_size - Bsz * NLAB;
    if (loff < 0) loff = 0;

    __half *ac, *h1c, *redch, *ctxc, *wh;
    float *h2c, *qc, *kc, *vc, *updc;
    cudaGetSymbolAddress((void**)&ac,    g_ac);
    cudaGetSymbolAddress((void**)&h1c,   g_h1c);
    cudaGetSymbolAddress((void**)&h2c,   g_h2c);
    cudaGetSymbolAddress((void**)&redch, g_redch);
    cudaGetSymbolAddress((void**)&qc,    g_qc);
    cudaGetSymbolAddress((void**)&kc,    g_kc);
    cudaGetSymbolAddress((void**)&vc,    g_vc);
    cudaGetSymbolAddress((void**)&ctxc,  g_ctxc);
    cudaGetSymbolAddress((void**)&updc,  g_updc);
    cudaGetSymbolAddress((void**)&wh,    g_wh);

    cudaFuncSetAttribute(mmagemm_k<1,0,1,1>, cudaFuncAttributeMaxDynamicSharedMemorySize, SMEM_DYN);
    cudaFuncSetAttribute(mmagemm_k<1,0,0,1>, cudaFuncAttributeMaxDynamicSharedMemorySize, SMEM_DYN);
    cudaFuncSetAttribute(mmagemm_k<0,3,0,1>, cudaFuncAttributeMaxDynamicSharedMemorySize, SMEM_DYN);
    cudaFuncSetAttribute(mmagemm_k<0,0,0,2>, cudaFuncAttributeMaxDynamicSharedMemorySize, SMEM_DYN);

    dim3 blk(256);
    // 0) prep
    prep_k<<<(Bsz + 255) / 256, 256>>>(mask);
    assign_k<<<(Mrows + 255) / 256, 256>>>(mask);
    acopy_k<<<(((Mrows + Ssz) * (Esz / 8)) + 255) / 256, 256>>>(cls, miss, mask);
    wprep_k<<<(WTOT + 255) / 256, 256>>>(W1, W2, Wq, Wk, Wv, Wo);
    // 1) GEMM1 + GELU (compacted) -> fp16 h1c  (N=384 -> 6 BN tiles)
    mmagemm_k<1,0,1,1><<<dim3(6, MCtiles), blk, SMEM_DYN>>>(
        ac, wh + OFF_W1, nullptr, nullptr, b1, nullptr, nullptr,
        h1c, nullptr, nullptr, 384, 768);
    // 2) GEMM2 + GELU (compacted) -> fp32 h2c  (N=256 -> 4 BN tiles)
    mmagemm_k<1,0,0,1><<<dim3(4, MCtiles), blk, SMEM_DYN>>>(
        h1c, wh + OFF_W2, nullptr, nullptr, b2, nullptr, nullptr,
        h2c, nullptr, nullptr, 256, 384);
    // 3) LayerNorm (compacted)
    ln_k<<<MCc / 8, 256>>>(lg, lb);
    // 4) fused QKV (compacted; q-branch only tile 0)  grid.x = 3*4
    mmagemm_k<0,3,0,1><<<dim3(12, MCtiles), blk, SMEM_DYN>>>(
        redch, wh + OFF_WQ, wh + OFF_WK, wh + OFF_WV, bq, bk, bv,
        qc, kc, vc, 256, 256);
    // 5) attention (only use-rows)
    attn_k<<<Bsz, 256>>>(mask);
    // 6) Wo projection over missing rows only -> updc
    mmagemm_k<0,0,0,2><<<dim3(4, Mrows/128), blk, SMEM_DYN>>>(
        ctxc, wh + OFF_WO, nullptr, nullptr, bo, nullptr, nullptr,
        updc, nullptr, nullptr, 256, 256);
    // 7) merged orthogonality loss + logits
    losslogit_k<<<Bsz, 256>>>(Wp, bp, out, loff);
    // 8) finalize loss scalar
    fin_k<<<1, 1>>>(out, loff >= 1 ? 1 : 0);
}

// round 16
// speedup vs baseline: 1.0144x; 1.0144x over previous
#include <cuda_runtime.h>
#include <cuda_fp16.h>
#include <math.h>
#include <stdint.h>

#define Bsz   2048
#define Ssz   23
#define Esz   768
#define REDsz 256
#define Hsz   8
#define DHsz  32
#define NLAB  25
#define Mrows (Bsz*Ssz)     // 47104
#define MCtiles 369
#define MCc   (MCtiles*128) // 47232

// GEMM pipeline config: fp16, BM=BN=128, BK=32, 5 stages, 2 CTAs/SM (R14 proven)
#define STAGES    5
#define ROWB      80
#define ATILE_B   (128*ROWB)
#define STAGE_B   (2*ATILE_B)
#define SMEM_DYN  (STAGES*STAGE_B)

// fp16 weight scratch offsets (halves)
#define W1N  (384*768)
#define W2N  (256*384)
#define WQN  (256*256)
#define OFF_W1 0
#define OFF_W2 (OFF_W1 + W1N)
#define OFF_WQ (OFF_W2 + W2N)
#define OFF_WK (OFF_WQ + WQN)
#define OFF_WV (OFF_WK + WQN)
#define OFF_WO (OFF_WV + WQN)
#define WTOT   (OFF_WO + WQN)

// ---------------- scratch (allocation-free; zero-initialized) ----------------
__device__ __half g_ac   [(size_t)MCc*768];
__device__ __half g_h1c  [(size_t)MCc*384];
__device__ float  g_h2c  [(size_t)MCc*256];
__device__ float  g_redc [(size_t)MCc*256];
__device__ __half g_redch[(size_t)MCc*256];
__device__ float  g_qc   [(size_t)MCc*256];
__device__ float  g_kc   [(size_t)MCc*256];
__device__ float  g_vc   [(size_t)MCc*256];
__device__ __half g_ctxc [(size_t)MCc*256];
__device__ float  g_updc [(size_t)MCc*256];
__device__ __half g_wh   [WTOT];
__device__ int    g_r2c  [Mrows];
__device__ int    g_m2c  [Mrows];
__device__ int    g_any  [Bsz];
__device__ int    g_cnt;
__device__ int    g_mcnt;
__device__ unsigned char g_use[Mrows];
__device__ float  g_acc;

__device__ __forceinline__ float gelu_f(float x) {
    return 0.5f * x * (1.0f + erff(x * 0.70710678118654752440f));
}

__device__ __forceinline__ uint32_t smem_u32(const void* p) {
    uint32_t a;
    asm("{ .reg .u64 t; cvta.to.shared.u64 t, %1; cvt.u32.u64 %0, t; }" : "=r"(a) : "l"(p));
    return a;
}

__device__ __forceinline__ void mma_f16(float* d, const uint32_t* a, const uint32_t* b) {
    asm volatile(
        "mma.sync.aligned.m16n8k16.row.col.f32.f16.f16.f32 "
        "{%0,%1,%2,%3}, {%4,%5,%6,%7}, {%8,%9}, {%0,%1,%2,%3};"
        : "+f"(d[0]), "+f"(d[1]), "+f"(d[2]), "+f"(d[3])
        : "r"(a[0]), "r"(a[1]), "r"(a[2]), "r"(a[3]), "r"(b[0]), "r"(b[1]));
}

#define LDSM_X4(r0_, r1_, r2_, r3_, addr_) \
    asm volatile("ldmatrix.sync.aligned.m8n8.x4.shared.b16 {%0,%1,%2,%3}, [%4];" \
                 : "=r"(r0_), "=r"(r1_), "=r"(r2_), "=r"(r3_) : "r"(addr_))
#define LDSM_X2(r0_, r1_, addr_) \
    asm volatile("ldmatrix.sync.aligned.m8n8.x2.shared.b16 {%0,%1}, [%2];" \
                 : "=r"(r0_), "=r"(r1_) : "r"(addr_))

#define CP_ASYNC16(dst_, src_) \
    asm volatile("cp.async.cg.shared.global [%0], [%1], 16;" :: "r"(dst_), "l"(src_) : "memory")
#define CP_COMMIT() asm volatile("cp.async.commit_group;" ::: "memory")
#define CP_WAIT(n_)  asm volatile("cp.async.wait_group %0;" :: "n"(n_) : "memory")

// ---------------- prep ----------------
__global__ void prep_k(const int* __restrict__ mask)
{
    int b = blockIdx.x * 256 + threadIdx.x;
    if (b == 0) { g_cnt = Ssz; g_mcnt = 0; }
    if (b >= Bsz) return;
    int a = 0;
    #pragma unroll
    for (int s = 0; s < Ssz; s++) a |= (mask[b * Ssz + s] > 0);
    g_any[b] = a;
}

__global__ void assign_k(const int* __restrict__ mask)
{
    int r = blockIdx.x * 256 + threadIdx.x;
    if (r >= Mrows) return;
    int exist = mask[r] > 0;
    if (exist) g_r2c[r] = atomicAdd(&g_cnt, 1);
    else       g_r2c[r] = r % Ssz;
    int use = (!exist) && g_any[r / Ssz];
    g_use[r] = (unsigned char)use;
    if (use) g_m2c[r] = atomicAdd(&g_mcnt, 1);
}

__global__ void acopy_k(const float* __restrict__ cls, const float* __restrict__ miss,
                        const int* __restrict__ mask)
{
    int idx = blockIdx.x * 256 + threadIdx.x;
    const int CH = Esz / 8;
    if (idx >= (Mrows + Ssz) * CH) return;
    const float* src; int drow, c;
    if (idx < Ssz * CH) {
        int s = idx / CH; c = (idx - s * CH) * 8;
        src = miss + (size_t)s * Esz + c; drow = s;
    } else {
        int j = idx - Ssz * CH;
        int r = j / CH; c = (j - r * CH) * 8;
        if (mask[r] <= 0) return;
        src = cls + (size_t)r * Esz + c; drow = g_r2c[r];
    }
    float4 v0 = *reinterpret_cast<const float4*>(src);
    float4 v1 = *reinterpret_cast<const float4*>(src + 4);
    __half2 h0 = __floats2half2_rn(v0.x, v0.y);
    __half2 h1 = __floats2half2_rn(v0.z, v0.w);
    __half2 h2 = __floats2half2_rn(v1.x, v1.y);
    __half2 h3 = __floats2half2_rn(v1.z, v1.w);
    uint4 o;
    o.x = *reinterpret_cast<uint32_t*>(&h0);
    o.y = *reinterpret_cast<uint32_t*>(&h1);
    o.z = *reinterpret_cast<uint32_t*>(&h2);
    o.w = *reinterpret_cast<uint32_t*>(&h3);
    *reinterpret_cast<uint4*>(&g_ac[(size_t)drow * Esz + c]) = o;
}

__global__ void wprep_k(const float* __restrict__ W1, const float* __restrict__ W2,
                        const float* __restrict__ Wq, const float* __restrict__ Wk,
                        const float* __restrict__ Wv, const float* __restrict__ Wo)
{
    int i = blockIdx.x * 256 + threadIdx.x;
    if (i >= WTOT) return;
    float v;
    if      (i < OFF_W2) v = W1[i - OFF_W1];
    else if (i < OFF_WQ) v = W2[i - OFF_W2];
    else if (i < OFF_WK) v = Wq[i - OFF_WQ];
    else if (i < OFF_WV) v = Wk[i - OFF_WK];
    else if (i < OFF_WO) v = Wv[i - OFF_WV];
    else                 v = Wo[i - OFF_WO];
    g_wh[i] = __float2half_rn(v);
}

// ---------------- HMMA fp16 GEMM, cp.async 5-stage pipeline (R14 config) ----------------
// BM=BN=128, BK=32 halves, 256 threads, warp tile 64x32.
// GUARD: 0 none, 1 exit if bm>=g_cnt, 2 exit if bm>=g_mcnt.
// MODE 0: plain. MODE 3: fused QKV (grid.x=6; q-branch only tile bm==0).
template<int ACT, int MODE, int OUTH, int GUARD>
__global__ void __launch_bounds__(256, 2) mmagemm_k(
    const __half* __restrict__ A,
    const __half* __restrict__ Wa, const __half* __restrict__ Wb, const __half* __restrict__ Wc,
    const float* __restrict__ ba, const float* __restrict__ bb, const float* __restrict__ bc,
    void* __restrict__ Cav, void* __restrict__ Cbv, void* __restrict__ Ccv,
    int N, int K)
{
    extern __shared__ char dynS[];

    const int bm = blockIdx.y * 128;
    if (GUARD == 1) { if (bm >= g_cnt)  return; }
    if (GUARD == 2) { if (bm >= g_mcnt) return; }

    const int tid  = threadIdx.x;
    const int lane = tid & 31;
    const int wid  = tid >> 5;
    const int g    = lane >> 2;
    const int tg   = lane & 3;
    const int wm   = wid & 1;
    const int wn   = wid >> 1;

    const __half* W; const float* bias; void* Cv; int bn;
    if (MODE == 3) {
        int sel = blockIdx.x >> 1;
        if (sel == 0 && bm > 0) return;     // q needed only for miss rows 0..22
        W    = sel == 0 ? Wa : sel == 1 ? Wb : Wc;
        bias = sel == 0 ? ba : sel == 1 ? bb : bc;
        Cv   = sel == 0 ? Cav : sel == 1 ? Cbv : Ccv;
        bn = (blockIdx.x & 1) * 128;
    } else {
        W = Wa; bias = ba; Cv = Cav;
        bn = blockIdx.x * 128;
    }

    const uint32_t sBase = smem_u32(dynS);

    const int lr = lane & 7;
    const int li = lane >> 3;
    const uint32_t aLd = sBase +
        (uint32_t)((wm * 64 + (li & 1) * 8 + lr) * ROWB + (li >> 1) * 16);
    const uint32_t bLd = sBase + ATILE_B +
        (uint32_t)((wn * 32 + lr) * ROWB + (li & 1) * 16);

    const int srow = tid >> 1;
    const int h16  = (tid & 1) * 16;
    const uint32_t aSt = sBase + (uint32_t)(srow * ROWB + (tid & 1) * 32);
    const uint32_t bSt = aSt + (uint32_t)ATILE_B;

    const __half* Arow = A + (size_t)(bm + srow) * K;
    const __half* Brow = W + (size_t)(bn + srow) * K;

    const int nT = K >> 5;

    #pragma unroll
    for (int t = 0; t < STAGES - 1; t++) {
        uint32_t so = (uint32_t)(t * STAGE_B);
        const __half* as = Arow + t * 32 + h16;
        const __half* bs = Brow + t * 32 + h16;
        CP_ASYNC16(aSt + so,      as);
        CP_ASYNC16(aSt + so + 16, as + 8);
        CP_ASYNC16(bSt + so,      bs);
        CP_ASYNC16(bSt + so + 16, bs + 8);
        CP_COMMIT();
    }

    float acc[4][4][4] = {};
    int cs = 0, is = STAGES - 1;

    for (int t = 0; t < nT; t++) {
        CP_WAIT(STAGES - 2);
        __syncthreads();

        int ft = t + STAGES - 1;
        if (ft < nT) {
            uint32_t so = (uint32_t)(is * STAGE_B);
            const __half* as = Arow + ft * 32 + h16;
            const __half* bs = Brow + ft * 32 + h16;
            CP_ASYNC16(aSt + so,      as);
            CP_ASYNC16(aSt + so + 16, as + 8);
            CP_ASYNC16(bSt + so,      bs);
            CP_ASYNC16(bSt + so + 16, bs + 8);
        }
        CP_COMMIT();
        if (++is == STAGES) is = 0;

        const uint32_t so = (uint32_t)(cs * STAGE_B);
        #pragma unroll
        for (int ks = 0; ks < 2; ks++) {
            const uint32_t kOff = so + (uint32_t)(ks * 32);
            uint32_t af[4][4];
            #pragma unroll
            for (int mt = 0; mt < 4; mt++)
                LDSM_X4(af[mt][0], af[mt][1], af[mt][2], af[mt][3],
                        aLd + (uint32_t)(mt * 16 * ROWB) + kOff);
            uint32_t bf[4][2];
            #pragma unroll
            for (int nt = 0; nt < 4; nt++)
                LDSM_X2(bf[nt][0], bf[nt][1],
                        bLd + (uint32_t)(nt * 8 * ROWB) + kOff);
            #pragma unroll
            for (int mt = 0; mt < 4; mt++)
                #pragma unroll
                for (int nt = 0; nt < 4; nt++)
                    mma_f16(acc[mt][nt], af[mt], bf[nt]);
        }
        if (++cs == STAGES) cs = 0;
    }

    #pragma unroll
    for (int mt = 0; mt < 4; mt++) {
        int m0 = bm + wm * 64 + mt * 16 + g;
        int m1 = m0 + 8;
        #pragma unroll
        for (int nt = 0; nt < 4; nt++) {
            int n = bn + wn * 32 + nt * 8 + 2 * tg;
            float2 bz = *reinterpret_cast<const float2*>(bias + n);
            float2 o0, o1;
            o0.x = acc[mt][nt][0] + bz.x; o0.y = acc[mt][nt][1] + bz.y;
            o1.x = acc[mt][nt][2] + bz.x; o1.y = acc[mt][nt][3] + bz.y;
            if (ACT == 1) {
                o0.x = gelu_f(o0.x); o0.y = gelu_f(o0.y);
                o1.x = gelu_f(o1.x); o1.y = gelu_f(o1.y);
            }
            if (OUTH) {
                __half* Ch = (__half*)Cv;
                __half2 h0 = __floats2half2_rn(o0.x, o0.y);
                __half2 h1 = __floats2half2_rn(o1.x, o1.y);
                *reinterpret_cast<__half2*>(&Ch[(size_t)m0 * N + n]) = h0;
                *reinterpret_cast<__half2*>(&Ch[(size_t)m1 * N + n]) = h1;
            } else {
                float* C = (float*)Cv;
                *reinterpret_cast<float2*>(&C[(size_t)m0 * N + n]) = o0;
                *reinterpret_cast<float2*>(&C[(size_t)m1 * N + n]) = o1;
            }
        }
    }
}

// ---------------- LayerNorm (compacted): one WARP per row ----------------
__global__ void ln_k(const float* __restrict__ gam, const float* __restrict__ bet)
{
    const int wid = threadIdx.x >> 5, lane = threadIdx.x & 31;
    const int r = blockIdx.x * 8 + wid;
    if (r >= g_cnt) return;
    const float* x = &g_h2c[(size_t)r * 256 + lane * 8];
    float4 v0 = *reinterpret_cast<const float4*>(x);
    float4 v1 = *reinterpret_cast<const float4*>(x + 4);
    float s = v0.x+v0.y+v0.z+v0.w + v1.x+v1.y+v1.z+v1.w;
    #pragma unroll
    for (int o = 16; o > 0; o >>= 1) s += __shfl_xor_sync(0xffffffffu, s, o);
    float mu = s * (1.0f / 256.0f);
    float d0x=v0.x-mu, d0y=v0.y-mu, d0z=v0.z-mu, d0w=v0.w-mu;
    float d1x=v1.x-mu, d1y=v1.y-mu, d1z=v1.z-mu, d1w=v1.w-mu;
    float sq = d0x*d0x+d0y*d0y+d0z*d0z+d0w*d0w + d1x*d1x+d1y*d1y+d1z*d1z+d1w*d1w;
    #pragma unroll
    for (int o = 16; o > 0; o >>= 1) sq += __shfl_xor_sync(0xffffffffu, sq, o);
    float rs = rsqrtf(sq * (1.0f / 256.0f) + 1e-5f);
    float4 ga0 = *reinterpret_cast<const float4*>(gam + lane * 8);
    float4 ga1 = *reinterpret_cast<const float4*>(gam + lane * 8 + 4);
    float4 be0 = *reinterpret_cast<const float4*>(bet + lane * 8);
    float4 be1 = *reinterpret_cast<const float4*>(bet + lane * 8 + 4);
    float4 o0, o1;
    o0.x = d0x*rs*ga0.x + be0.x; o0.y = d0y*rs*ga0.y + be0.y;
    o0.z = d0z*rs*ga0.z + be0.z; o0.w = d0w*rs*ga0.w + be0.w;
    o1.x = d1x*rs*ga1.x + be1.x; o1.y = d1y*rs*ga1.y + be1.y;
    o1.z = d1z*rs*ga1.z + be1.z; o1.w = d1w*rs*ga1.w + be1.w;
    float* y = &g_redc[(size_t)r * 256 + lane * 8];
    *reinterpret_cast<float4*>(y)     = o0;
    *reinterpret_cast<float4*>(y + 4) = o1;
    __half2 h0 = __floats2half2_rn(o0.x, o0.y);
    __half2 h1 = __floats2half2_rn(o0.z, o0.w);
    __half2 h2 = __floats2half2_rn(o1.x, o1.y);
    __half2 h3 = __floats2half2_rn(o1.z, o1.w);
    uint4 hv;
    hv.x = *reinterpret_cast<uint32_t*>(&h0);
    hv.y = *reinterpret_cast<uint32_t*>(&h1);
    hv.z = *reinterpret_cast<uint32_t*>(&h2);
    hv.w = *reinterpret_cast<uint32_t*>(&h3);
    *reinterpret_cast<uint4*>(&g_redch[(size_t)r * 256 + lane * 8]) = hv;
}

// ---------------- attention: block per batch, warp per head, only use-rows ----------------
__global__ void attn_k(const int* __restrict__ mask)
{
    int b = blockIdx.x, tid = threadIdx.x;
    int h = tid >> 5, lane = tid & 31;
    __shared__ float qs[Hsz][Ssz][33], ks[Hsz][Ssz][33], vs[Hsz][Ssz][33];
    __shared__ float sc[Hsz][Ssz][Ssz + 1];
    __shared__ int exS[Ssz], useS[Ssz], idxS[Ssz], midS[Ssz];

    if (b == 0 && tid == 0) g_acc = 0.0f;
    if (tid < Ssz) {
        int r = b * Ssz + tid;
        exS[tid]  = (mask[r] > 0);
        useS[tid] = g_use[r];
        idxS[tid] = g_r2c[r];
        midS[tid] = g_use[r] ? g_m2c[r] : 0;
    }
    __syncthreads();
    if (!g_any[b]) return;

    #pragma unroll
    for (int s = 0; s < Ssz; s++) {
        size_t base = (size_t)idxS[s] * REDsz + h * DHsz + lane;
        if (exS[s]) {                    // masked keys never contribute
            ks[h][s][lane] = g_kc[base];
            vs[h][s][lane] = g_vc[base];
        } else {
            vs[h][s][lane] = 0.0f;       // weight exactly 0; avoid garbage*0
        }
        if (useS[s]) qs[h][s][lane] = g_qc[base];
    }
    __syncwarp();

    for (int idx = lane; idx < Ssz * Ssz; idx += 32) {
        int i = idx / Ssz, j = idx - i * Ssz;
        if (!useS[i]) continue;
        if (exS[j]) {
            float dot = 0.0f;
            #pragma unroll
            for (int d = 0; d < 32; d++) dot += qs[h][i][d] * ks[h][j][d];
            sc[h][i][j] = dot * 0.17677669529663687f;
        } else {
            sc[h][i][j] = -1e9f;
        }
    }
    __syncwarp();

    if (lane < Ssz && useS[lane]) {
        int i = lane;
        float m = -1e30f;
        #pragma unroll
        for (int j = 0; j < Ssz; j++) m = fmaxf(m, sc[h][i][j]);
        float sum = 0.0f;
        #pragma unroll
        for (int j = 0; j < Ssz; j++) { float e = expf(sc[h][i][j] - m); sc[h][i][j] = e; sum += e; }
        float inv = 1.0f / sum;
        #pragma unroll
        for (int j = 0; j < Ssz; j++) sc[h][i][j] *= inv;
    }
    __syncwarp();

    #pragma unroll
    for (int i = 0; i < Ssz; i++) {
        if (!useS[i]) continue;
        float s = 0.0f;
        #pragma unroll
        for (int j = 0; j < Ssz; j++) s += sc[h][i][j] * vs[h][j][lane];
        g_ctxc[(size_t)midS[i] * REDsz + h * DHsz + lane] = __float2half_rn(s);
    }
}

// ---------------- merged orthogonality loss + logits (float4 dots) ----------------
__global__ void losslogit_k(const float* __restrict__ Wp, const float* __restrict__ bp,
                            float* __restrict__ out, int loff)
{
    int b = blockIdx.x, tid = threadIdx.x;
    __shared__ __align__(16) float X[Ssz][260];
    __shared__ float inv[Ssz];
    __shared__ float mean[REDsz];
    __shared__ const float* srcS[Ssz];
    if (tid < Ssz) {
        int r = b * Ssz + tid;
        srcS[tid] = g_use[r] ? &g_updc[(size_t)g_m2c[r] * 256]
                             : &g_redc[(size_t)g_r2c[r] * 256];
    }
    __syncthreads();
    for (int idx = tid; idx < Ssz * REDsz; idx += 256) {
        int s = idx >> 8, d = idx & 255;
        X[s][d] = srcS[s][d];
    }
    __syncthreads();
    int w = tid >> 5, lane = tid & 31;
    for (int r = w; r < Ssz; r += 8) {
        float s = 0.0f;
        for (int d = lane; d < 256; d += 32) s += X[r][d] * X[r][d];
        for (int o = 16; o > 0; o >>= 1) s += __shfl_down_sync(0xffffffffu, s, o);
        if (lane == 0) inv[r] = 1.0f / fmaxf(sqrtf(s), 1e-8f);
    }
    {
        float s = 0.0f;
        #pragma unroll
        for (int ss = 0; ss < Ssz; ss++) s += X[ss][tid];
        mean[tid] = s * (1.0f / (float)Ssz);
    }
    __syncthreads();
    float part = 0.0f;
    if (tid < (Ssz * (Ssz - 1)) / 2) {
        int p = tid, i = 0;
        while (p >= Ssz - 1 - i) { p -= Ssz - 1 - i; i++; }
        int j = i + 1 + p;
        const float4* xi = reinterpret_cast<const float4*>(&X[i][0]);
        const float4* xj = reinterpret_cast<const float4*>(&X[j][0]);
        float dot = 0.0f;
        #pragma unroll 8
        for (int d = 0; d < 64; d++) {
            float4 a = xi[d], c = xj[d];
            dot += a.x*c.x + a.y*c.y + a.z*c.z + a.w*c.w;
        }
        float gv = fabsf(dot * inv[i] * inv[j]);
        part = fmaxf(gv - 0.1f, 0.0f) * 2.0f;
    }
    __shared__ float red[256];
    red[tid] = part; __syncthreads();
    for (int s = 128; s > 0; s >>= 1) { if (tid < s) red[tid] += red[tid + s]; __syncthreads(); }
    if (tid == 0) atomicAdd(&g_acc, red[0]);
    if (tid < NLAB) {
        float a = bp[tid];
        const float* wr = Wp + tid * REDsz;
        for (int d = 0; d < REDsz; d++) a += mean[d] * wr[d];
        out[loff + b * NLAB + tid] = a;
    }
}

__global__ void fin_k(float* out, int writeloss)
{
    if (writeloss)
        out[0] = g_acc * (1.0f / ((float)Bsz * Ssz * (Ssz - 1)));
}

// ---------------- launch ----------------
extern "C" void kernel_launch(void* const* d_in, const int* in_sizes, int n_in,
                              void* d_out, int out_size)
{
    const float* cls  = (const float*)d_in[0];
    const int*   mask = (const int*)  d_in[1];
    const float* miss = (const float*)d_in[2];
    const float* W1 = (const float*)d_in[3];  const float* b1 = (const float*)d_in[4];
    const float* W2 = (const float*)d_in[5];  const float* b2 = (const float*)d_in[6];
    const float* lg = (const float*)d_in[7];  const float* lb = (const float*)d_in[8];
    const float* Wq = (const float*)d_in[9];  const float* bq = (const float*)d_in[10];
    const float* Wk = (const float*)d_in[11]; const float* bk = (const float*)d_in[12];
    const float* Wv = (const float*)d_in[13]; const float* bv = (const float*)d_in[14];
    const float* Wo = (const float*)d_in[15]; const float* bo = (const float*)d_in[16];
    const float* Wp = (const float*)d_in[17]; const float* bp = (const float*)d_in[18];
    float* out = (float*)d_out;

    int loff = out_size - Bsz * NLAB;
    if (loff < 0) loff = 0;

    __half *ac, *h1c, *redch, *ctxc, *wh;
    float *h2c, *qc, *kc, *vc, *updc;
    cudaGetSymbolAddress((void**)&ac,    g_ac);
    cudaGetSymbolAddress((void**)&h1c,   g_h1c);
    cudaGetSymbolAddress((void**)&h2c,   g_h2c);
    cudaGetSymbolAddress((void**)&redch, g_redch);
    cudaGetSymbolAddress((void**)&qc,    g_qc);
    cudaGetSymbolAddress((void**)&kc,    g_kc);
    cudaGetSymbolAddress((void**)&vc,    g_vc);
    cudaGetSymbolAddress((void**)&ctxc,  g_ctxc);
    cudaGetSymbolAddress((void**)&updc,  g_updc);
    cudaGetSymbolAddress((void**)&wh,    g_wh);

    cudaFuncSetAttribute(mmagemm_k<1,0,1,1>, cudaFuncAttributeMaxDynamicSharedMemorySize, SMEM_DYN);
    cudaFuncSetAttribute(mmagemm_k<1,0,0,1>, cudaFuncAttributeMaxDynamicSharedMemorySize, SMEM_DYN);
    cudaFuncSetAttribute(mmagemm_k<0,3,0,1>, cudaFuncAttributeMaxDynamicSharedMemorySize, SMEM_DYN);
    cudaFuncSetAttribute(mmagemm_k<0,0,0,2>, cudaFuncAttributeMaxDynamicSharedMemorySize, SMEM_DYN);

    dim3 blk(256);
    // 0) prep
    prep_k<<<(Bsz + 255) / 256, 256>>>(mask);
    assign_k<<<(Mrows + 255) / 256, 256>>>(mask);
    acopy_k<<<(((Mrows + Ssz) * (Esz / 8)) + 255) / 256, 256>>>(cls, miss, mask);
    wprep_k<<<(WTOT + 255) / 256, 256>>>(W1, W2, Wq, Wk, Wv, Wo);
    // 1) GEMM1 + GELU (compacted) -> fp16 h1c
    mmagemm_k<1,0,1,1><<<dim3(3, MCtiles), blk, SMEM_DYN>>>(
        ac, wh + OFF_W1, nullptr, nullptr, b1, nullptr, nullptr,
        h1c, nullptr, nullptr, 384, 768);
    // 2) GEMM2 + GELU (compacted) -> fp32 h2c
    mmagemm_k<1,0,0,1><<<dim3(2, MCtiles), blk, SMEM_DYN>>>(
        h1c, wh + OFF_W2, nullptr, nullptr, b2, nullptr, nullptr,
        h2c, nullptr, nullptr, 256, 384);
    // 3) LayerNorm (compacted)
    ln_k<<<MCc / 8, 256>>>(lg, lb);
    // 4) fused QKV (compacted; q-branch only tile 0)
    mmagemm_k<0,3,0,1><<<dim3(6, MCtiles), blk, SMEM_DYN>>>(
        redch, wh + OFF_WQ, wh + OFF_WK, wh + OFF_WV, bq, bk, bv,
        qc, kc, vc, 256, 256);
    // 5) attention (only use-rows)
    attn_k<<<Bsz, 256>>>(mask);
    // 6) Wo projection over missing rows only -> updc
    mmagemm_k<0,0,0,2><<<dim3(2, Mrows/128), blk, SMEM_DYN>>>(
        ctxc, wh + OFF_WO, nullptr, nullptr, bo, nullptr, nullptr,
        updc, nullptr, nullptr, 256, 256);
    // 7) merged orthogonality loss + logits
    losslogit_k<<<Bsz, 256>>>(Wp, bp, out, loff);
    // 8) finalize loss scalar
    fin_k<<<1, 1>>>(out, loff >= 1 ? 1 : 0);
}

// round 17
// speedup vs baseline: 1.0605x; 1.0454x over previous
#include <cuda_runtime.h>
#include <cuda_fp16.h>
#include <math.h>
#include <stdint.h>

#define Bsz   2048
#define Ssz   23
#define Esz   768
#define REDsz 256
#define Hsz   8
#define DHsz  32
#define NLAB  25
#define Mrows (Bsz*Ssz)     // 47104
#define MCtiles 369
#define MCc   (MCtiles*128) // 47232

// GEMM pipeline config (proven R14): fp16, BM=BN=128, BK=32, 5 stages, 2 CTAs/SM
#define STAGES    5
#define ROWB      80
#define ATILE_B   (128*ROWB)
#define STAGE_B   (2*ATILE_B)
#define SMEM_DYN  (STAGES*STAGE_B)

// fused GEMM2+LN config: BM=64, BN=256, BK=32, 4 stages
#define STAGES2   4
#define A2TILE    (64*ROWB)             // 5120
#define B2TILE    (256*ROWB)            // 20480
#define STAGE2    (A2TILE + B2TILE)     // 25600
#define SMEM2     (STAGES2*STAGE2)      // 102400 (>= 64*260*4 epilogue buf)

// fp16 weight scratch offsets (halves)
#define W1N  (384*768)
#define W2N  (256*384)
#define WQN  (256*256)
#define OFF_W1 0
#define OFF_W2 (OFF_W1 + W1N)
#define OFF_WQ (OFF_W2 + W2N)
#define OFF_WK (OFF_WQ + WQN)
#define OFF_WV (OFF_WK + WQN)
#define OFF_WO (OFF_WV + WQN)
#define WTOT   (OFF_WO + WQN)

// ---------------- scratch (allocation-free; zero-initialized) ----------------
__device__ __half g_ac   [(size_t)MCc*768];
__device__ __half g_h1c  [(size_t)MCc*384];
__device__ float  g_redc [(size_t)MCc*256];
__device__ __half g_redch[(size_t)MCc*256];
__device__ float  g_qc   [(size_t)MCc*256];
__device__ float  g_kc   [(size_t)MCc*256];
__device__ float  g_vc   [(size_t)MCc*256];
__device__ __half g_ctxc [(size_t)MCc*256];
__device__ float  g_updc [(size_t)MCc*256];
__device__ __half g_wh   [WTOT];
__device__ int    g_r2c  [Mrows];
__device__ int    g_m2c  [Mrows];
__device__ int    g_any  [Bsz];
__device__ int    g_cnt;
__device__ int    g_mcnt;
__device__ unsigned char g_use[Mrows];
__device__ float  g_acc;

__device__ __forceinline__ float gelu_f(float x) {
    return 0.5f * x * (1.0f + erff(x * 0.70710678118654752440f));
}

__device__ __forceinline__ uint32_t smem_u32(const void* p) {
    uint32_t a;
    asm("{ .reg .u64 t; cvta.to.shared.u64 t, %1; cvt.u32.u64 %0, t; }" : "=r"(a) : "l"(p));
    return a;
}

__device__ __forceinline__ void mma_f16(float* d, const uint32_t* a, const uint32_t* b) {
    asm volatile(
        "mma.sync.aligned.m16n8k16.row.col.f32.f16.f16.f32 "
        "{%0,%1,%2,%3}, {%4,%5,%6,%7}, {%8,%9}, {%0,%1,%2,%3};"
        : "+f"(d[0]), "+f"(d[1]), "+f"(d[2]), "+f"(d[3])
        : "r"(a[0]), "r"(a[1]), "r"(a[2]), "r"(a[3]), "r"(b[0]), "r"(b[1]));
}

#define LDSM_X4(r0_, r1_, r2_, r3_, addr_) \
    asm volatile("ldmatrix.sync.aligned.m8n8.x4.shared.b16 {%0,%1,%2,%3}, [%4];" \
                 : "=r"(r0_), "=r"(r1_), "=r"(r2_), "=r"(r3_) : "r"(addr_))
#define LDSM_X2(r0_, r1_, addr_) \
    asm volatile("ldmatrix.sync.aligned.m8n8.x2.shared.b16 {%0,%1}, [%2];" \
                 : "=r"(r0_), "=r"(r1_) : "r"(addr_))

#define CP_ASYNC16(dst_, src_) \
    asm volatile("cp.async.cg.shared.global [%0], [%1], 16;" :: "r"(dst_), "l"(src_) : "memory")
#define CP_COMMIT() asm volatile("cp.async.commit_group;" ::: "memory")
#define CP_WAIT(n_)  asm volatile("cp.async.wait_group %0;" :: "n"(n_) : "memory")

// ---------------- prep ----------------
__global__ void prep_k(const int* __restrict__ mask)
{
    int b = blockIdx.x * 256 + threadIdx.x;
    if (b == 0) { g_cnt = Ssz; g_mcnt = 0; }
    if (b >= Bsz) return;
    int a = 0;
    #pragma unroll
    for (int s = 0; s < Ssz; s++) a |= (mask[b * Ssz + s] > 0);
    g_any[b] = a;
}

__global__ void assign_k(const int* __restrict__ mask)
{
    int r = blockIdx.x * 256 + threadIdx.x;
    if (r >= Mrows) return;
    int exist = mask[r] > 0;
    if (exist) g_r2c[r] = atomicAdd(&g_cnt, 1);
    else       g_r2c[r] = r % Ssz;
    int use = (!exist) && g_any[r / Ssz];
    g_use[r] = (unsigned char)use;
    if (use) g_m2c[r] = atomicAdd(&g_mcnt, 1);
}

__global__ void acopy_k(const float* __restrict__ cls, const float* __restrict__ miss,
                        const int* __restrict__ mask)
{
    int idx = blockIdx.x * 256 + threadIdx.x;
    const int CH = Esz / 8;
    if (idx >= (Mrows + Ssz) * CH) return;
    const float* src; int drow, c;
    if (idx < Ssz * CH) {
        int s = idx / CH; c = (idx - s * CH) * 8;
        src = miss + (size_t)s * Esz + c; drow = s;
    } else {
        int j = idx - Ssz * CH;
        int r = j / CH; c = (j - r * CH) * 8;
        if (mask[r] <= 0) return;
        src = cls + (size_t)r * Esz + c; drow = g_r2c[r];
    }
    float4 v0 = *reinterpret_cast<const float4*>(src);
    float4 v1 = *reinterpret_cast<const float4*>(src + 4);
    __half2 h0 = __floats2half2_rn(v0.x, v0.y);
    __half2 h1 = __floats2half2_rn(v0.z, v0.w);
    __half2 h2 = __floats2half2_rn(v1.x, v1.y);
    __half2 h3 = __floats2half2_rn(v1.z, v1.w);
    uint4 o;
    o.x = *reinterpret_cast<uint32_t*>(&h0);
    o.y = *reinterpret_cast<uint32_t*>(&h1);
    o.z = *reinterpret_cast<uint32_t*>(&h2);
    o.w = *reinterpret_cast<uint32_t*>(&h3);
    *reinterpret_cast<uint4*>(&g_ac[(size_t)drow * Esz + c]) = o;
}

__global__ void wprep_k(const float* __restrict__ W1, const float* __restrict__ W2,
                        const float* __restrict__ Wq, const float* __restrict__ Wk,
                        const float* __restrict__ Wv, const float* __restrict__ Wo)
{
    int i = blockIdx.x * 256 + threadIdx.x;
    if (i >= WTOT) return;
    float v;
    if      (i < OFF_W2) v = W1[i - OFF_W1];
    else if (i < OFF_WQ) v = W2[i - OFF_W2];
    else if (i < OFF_WK) v = Wq[i - OFF_WQ];
    else if (i < OFF_WV) v = Wk[i - OFF_WK];
    else if (i < OFF_WO) v = Wv[i - OFF_WV];
    else                 v = Wo[i - OFF_WO];
    g_wh[i] = __float2half_rn(v);
}

// ---------------- HMMA fp16 GEMM, cp.async 5-stage pipeline (R14 proven) ----------------
// BM=BN=128, BK=32 halves, 256 threads, warp tile 64x32.
// GUARD: 0 none, 1 exit if bm>=g_cnt, 2 exit if bm>=g_mcnt.
// MODE 0: plain. MODE 3: fused QKV (grid.x=6; q-branch only tile bm==0).
template<int ACT, int MODE, int OUTH, int GUARD>
__global__ void __launch_bounds__(256, 2) mmagemm_k(
    const __half* __restrict__ A,
    const __half* __restrict__ Wa, const __half* __restrict__ Wb, const __half* __restrict__ Wc,
    const float* __restrict__ ba, const float* __restrict__ bb, const float* __restrict__ bc,
    void* __restrict__ Cav, void* __restrict__ Cbv, void* __restrict__ Ccv,
    int N, int K)
{
    extern __shared__ char dynS[];

    const int bm = blockIdx.y * 128;
    if (GUARD == 1) { if (bm >= g_cnt)  return; }
    if (GUARD == 2) { if (bm >= g_mcnt) return; }

    const int tid  = threadIdx.x;
    const int lane = tid & 31;
    const int wid  = tid >> 5;
    const int g    = lane >> 2;
    const int tg   = lane & 3;
    const int wm   = wid & 1;
    const int wn   = wid >> 1;

    const __half* W; const float* bias; void* Cv; int bn;
    if (MODE == 3) {
        int sel = blockIdx.x >> 1;
        if (sel == 0 && bm > 0) return;
        W    = sel == 0 ? Wa : sel == 1 ? Wb : Wc;
        bias = sel == 0 ? ba : sel == 1 ? bb : bc;
        Cv   = sel == 0 ? Cav : sel == 1 ? Cbv : Ccv;
        bn = (blockIdx.x & 1) * 128;
    } else {
        W = Wa; bias = ba; Cv = Cav;
        bn = blockIdx.x * 128;
    }

    const uint32_t sBase = smem_u32(dynS);

    const int lr = lane & 7;
    const int li = lane >> 3;
    const uint32_t aLd = sBase +
        (uint32_t)((wm * 64 + (li & 1) * 8 + lr) * ROWB + (li >> 1) * 16);
    const uint32_t bLd = sBase + ATILE_B +
        (uint32_t)((wn * 32 + lr) * ROWB + (li & 1) * 16);

    const int srow = tid >> 1;
    const int h16  = (tid & 1) * 16;
    const uint32_t aSt = sBase + (uint32_t)(srow * ROWB + (tid & 1) * 32);
    const uint32_t bSt = aSt + (uint32_t)ATILE_B;

    const __half* Arow = A + (size_t)(bm + srow) * K;
    const __half* Brow = W + (size_t)(bn + srow) * K;

    const int nT = K >> 5;

    #pragma unroll
    for (int t = 0; t < STAGES - 1; t++) {
        uint32_t so = (uint32_t)(t * STAGE_B);
        const __half* as = Arow + t * 32 + h16;
        const __half* bs = Brow + t * 32 + h16;
        CP_ASYNC16(aSt + so,      as);
        CP_ASYNC16(aSt + so + 16, as + 8);
        CP_ASYNC16(bSt + so,      bs);
        CP_ASYNC16(bSt + so + 16, bs + 8);
        CP_COMMIT();
    }

    float acc[4][4][4] = {};
    int cs = 0, is = STAGES - 1;

    for (int t = 0; t < nT; t++) {
        CP_WAIT(STAGES - 2);
        __syncthreads();

        int ft = t + STAGES - 1;
        if (ft < nT) {
            uint32_t so = (uint32_t)(is * STAGE_B);
            const __half* as = Arow + ft * 32 + h16;
            const __half* bs = Brow + ft * 32 + h16;
            CP_ASYNC16(aSt + so,      as);
            CP_ASYNC16(aSt + so + 16, as + 8);
            CP_ASYNC16(bSt + so,      bs);
            CP_ASYNC16(bSt + so + 16, bs + 8);
        }
        CP_COMMIT();
        if (++is == STAGES) is = 0;

        const uint32_t so = (uint32_t)(cs * STAGE_B);
        #pragma unroll
        for (int ks = 0; ks < 2; ks++) {
            const uint32_t kOff = so + (uint32_t)(ks * 32);
            uint32_t af[4][4];
            #pragma unroll
            for (int mt = 0; mt < 4; mt++)
                LDSM_X4(af[mt][0], af[mt][1], af[mt][2], af[mt][3],
                        aLd + (uint32_t)(mt * 16 * ROWB) + kOff);
            uint32_t bf[4][2];
            #pragma unroll
            for (int nt = 0; nt < 4; nt++)
                LDSM_X2(bf[nt][0], bf[nt][1],
                        bLd + (uint32_t)(nt * 8 * ROWB) + kOff);
            #pragma unroll
            for (int mt = 0; mt < 4; mt++)
                #pragma unroll
                for (int nt = 0; nt < 4; nt++)
                    mma_f16(acc[mt][nt], af[mt], bf[nt]);
        }
        if (++cs == STAGES) cs = 0;
    }

    #pragma unroll
    for (int mt = 0; mt < 4; mt++) {
        int m0 = bm + wm * 64 + mt * 16 + g;
        int m1 = m0 + 8;
        #pragma unroll
        for (int nt = 0; nt < 4; nt++) {
            int n = bn + wn * 32 + nt * 8 + 2 * tg;
            float2 bz = *reinterpret_cast<const float2*>(bias + n);
            float2 o0, o1;
            o0.x = acc[mt][nt][0] + bz.x; o0.y = acc[mt][nt][1] + bz.y;
            o1.x = acc[mt][nt][2] + bz.x; o1.y = acc[mt][nt][3] + bz.y;
            if (ACT == 1) {
                o0.x = gelu_f(o0.x); o0.y = gelu_f(o0.y);
                o1.x = gelu_f(o1.x); o1.y = gelu_f(o1.y);
            }
            if (OUTH) {
                __half* Ch = (__half*)Cv;
                __half2 h0 = __floats2half2_rn(o0.x, o0.y);
                __half2 h1 = __floats2half2_rn(o1.x, o1.y);
                *reinterpret_cast<__half2*>(&Ch[(size_t)m0 * N + n]) = h0;
                *reinterpret_cast<__half2*>(&Ch[(size_t)m1 * N + n]) = h1;
            } else {
                float* C = (float*)Cv;
                *reinterpret_cast<float2*>(&C[(size_t)m0 * N + n]) = o0;
                *reinterpret_cast<float2*>(&C[(size_t)m1 * N + n]) = o1;
            }
        }
    }
}

// ---------------- fused GEMM2 + GELU + LayerNorm ----------------
// BM=64, BN=256 (full row), BK=32, 4 stages, warp tile 64x32 (wn=wid).
// Epilogue: gelu -> smem buf[64][260] -> warp-per-row LN -> redc + redch.
__global__ void __launch_bounds__(256, 2) gemm2ln_k(
    const __half* __restrict__ A, const __half* __restrict__ W,
    const float* __restrict__ bias,
    const float* __restrict__ gam, const float* __restrict__ bet)
{
    extern __shared__ char dynS[];

    const int bm = blockIdx.y * 64;
    if (bm >= g_cnt) return;

    const int tid  = threadIdx.x;
    const int lane = tid & 31;
    const int wid  = tid >> 5;      // = n-block (32 cols)
    const int g    = lane >> 2;
    const int tg   = lane & 3;
    const int K    = 384;

    const uint32_t sBase = smem_u32(dynS);

    const int lr = lane & 7;
    const int li = lane >> 3;
    const uint32_t aLd = sBase +
        (uint32_t)(((li & 1) * 8 + lr) * ROWB + (li >> 1) * 16);
    const uint32_t bLd = sBase + A2TILE +
        (uint32_t)((wid * 32 + lr) * ROWB + (li & 1) * 16);

    // staging: A 1 chunk/thread, B 4 chunks/thread
    const int arow = tid >> 2;
    const int ach  = tid & 3;
    const uint32_t aSt = sBase + (uint32_t)(arow * ROWB + ach * 16);
    const __half* Asrc = A + (size_t)(bm + arow) * K + ach * 8;
    const uint32_t bSt = sBase + A2TILE + (uint32_t)(arow * ROWB + ach * 16);
    const __half* Bsrc = W + (size_t)arow * K + ach * 8;

    const int nT = K >> 5;   // 12

    #pragma unroll
    for (int t = 0; t < STAGES2 - 1; t++) {
        uint32_t so = (uint32_t)(t * STAGE2);
        CP_ASYNC16(aSt + so, Asrc + t * 32);
        #pragma unroll
        for (int j = 0; j < 4; j++)
            CP_ASYNC16(bSt + so + (uint32_t)(j * 64 * ROWB),
                       Bsrc + (size_t)j * 64 * K + t * 32);
        CP_COMMIT();
    }

    float acc[4][4][4] = {};
    int cs = 0, is = STAGES2 - 1;

    for (int t = 0; t < nT; t++) {
        CP_WAIT(STAGES2 - 2);
        __syncthreads();

        int ft = t + STAGES2 - 1;
        if (ft < nT) {
            uint32_t so = (uint32_t)(is * STAGE2);
            CP_ASYNC16(aSt + so, Asrc + ft * 32);
            #pragma unroll
            for (int j = 0; j < 4; j++)
                CP_ASYNC16(bSt + so + (uint32_t)(j * 64 * ROWB),
                           Bsrc + (size_t)j * 64 * K + ft * 32);
        }
        CP_COMMIT();
        if (++is == STAGES2) is = 0;

        const uint32_t so = (uint32_t)(cs * STAGE2);
        #pragma unroll
        for (int ks = 0; ks < 2; ks++) {
            const uint32_t kOff = so + (uint32_t)(ks * 32);
            uint32_t af[4][4];
            #pragma unroll
            for (int mt = 0; mt < 4; mt++)
                LDSM_X4(af[mt][0], af[mt][1], af[mt][2], af[mt][3],
                        aLd + (uint32_t)(mt * 16 * ROWB) + kOff);
            uint32_t bf[4][2];
            #pragma unroll
            for (int nt = 0; nt < 4; nt++)
                LDSM_X2(bf[nt][0], bf[nt][1],
                        bLd + (uint32_t)(nt * 8 * ROWB) + kOff);
            #pragma unroll
            for (int mt = 0; mt < 4; mt++)
                #pragma unroll
                for (int nt = 0; nt < 4; nt++)
                    mma_f16(acc[mt][nt], af[mt], bf[nt]);
        }
        if (++cs == STAGES2) cs = 0;
    }

    // drain pipeline, then reuse smem as epilogue buffer
    CP_WAIT(0);
    __syncthreads();

    float* buf = reinterpret_cast<float*>(dynS);   // [64][260]
    #pragma unroll
    for (int mt = 0; mt < 4; mt++) {
        int m0 = mt * 16 + g;
        int m1 = m0 + 8;
        #pragma unroll
        for (int nt = 0; nt < 4; nt++) {
            int n = wid * 32 + nt * 8 + 2 * tg;
            float2 bz = *reinterpret_cast<const float2*>(bias + n);
            float2 o0, o1;
            o0.x = gelu_f(acc[mt][nt][0] + bz.x);
            o0.y = gelu_f(acc[mt][nt][1] + bz.y);
            o1.x = gelu_f(acc[mt][nt][2] + bz.x);
            o1.y = gelu_f(acc[mt][nt][3] + bz.y);
            *reinterpret_cast<float2*>(&buf[m0 * 260 + n]) = o0;
            *reinterpret_cast<float2*>(&buf[m1 * 260 + n]) = o1;
        }
    }
    __syncthreads();

    // warp-per-row LayerNorm over 256, 8 rows per warp
    #pragma unroll
    for (int it = 0; it < 8; it++) {
        int r = wid * 8 + it;
        const float* x = &buf[r * 260 + lane * 8];
        float4 v0 = *reinterpret_cast<const float4*>(x);
        float4 v1 = *reinterpret_cast<const float4*>(x + 4);
        float s = v0.x+v0.y+v0.z+v0.w + v1.x+v1.y+v1.z+v1.w;
        #pragma unroll
        for (int o = 16; o > 0; o >>= 1) s += __shfl_xor_sync(0xffffffffu, s, o);
        float mu = s * (1.0f / 256.0f);
        float d0x=v0.x-mu, d0y=v0.y-mu, d0z=v0.z-mu, d0w=v0.w-mu;
        float d1x=v1.x-mu, d1y=v1.y-mu, d1z=v1.z-mu, d1w=v1.w-mu;
        float sq = d0x*d0x+d0y*d0y+d0z*d0z+d0w*d0w + d1x*d1x+d1y*d1y+d1z*d1z+d1w*d1w;
        #pragma unroll
        for (int o = 16; o > 0; o >>= 1) sq += __shfl_xor_sync(0xffffffffu, sq, o);
        float rs = rsqrtf(sq * (1.0f / 256.0f) + 1e-5f);
        float4 ga0 = *reinterpret_cast<const float4*>(gam + lane * 8);
        float4 ga1 = *reinterpret_cast<const float4*>(gam + lane * 8 + 4);
        float4 be0 = *reinterpret_cast<const float4*>(bet + lane * 8);
        float4 be1 = *reinterpret_cast<const float4*>(bet + lane * 8 + 4);
        float4 o0, o1;
        o0.x = d0x*rs*ga0.x + be0.x; o0.y = d0y*rs*ga0.y + be0.y;
        o0.z = d0z*rs*ga0.z + be0.z; o0.w = d0w*rs*ga0.w + be0.w;
        o1.x = d1x*rs*ga1.x + be1.x; o1.y = d1y*rs*ga1.y + be1.y;
        o1.z = d1z*rs*ga1.z + be1.z; o1.w = d1w*rs*ga1.w + be1.w;
        float* y = &g_redc[(size_t)(bm + r) * 256 + lane * 8];
        *reinterpret_cast<float4*>(y)     = o0;
        *reinterpret_cast<float4*>(y + 4) = o1;
        __half2 h0 = __floats2half2_rn(o0.x, o0.y);
        __half2 h1 = __floats2half2_rn(o0.z, o0.w);
        __half2 h2 = __floats2half2_rn(o1.x, o1.y);
        __half2 h3 = __floats2half2_rn(o1.z, o1.w);
        uint4 hv;
        hv.x = *reinterpret_cast<uint32_t*>(&h0);
        hv.y = *reinterpret_cast<uint32_t*>(&h1);
        hv.z = *reinterpret_cast<uint32_t*>(&h2);
        hv.w = *reinterpret_cast<uint32_t*>(&h3);
        *reinterpret_cast<uint4*>(&g_redch[(size_t)(bm + r) * 256 + lane * 8]) = hv;
    }
}

// ---------------- attention: block per batch, warp per head, only use-rows (R14) ----------------
__global__ void attn_k(const int* __restrict__ mask)
{
    int b = blockIdx.x, tid = threadIdx.x;
    int h = tid >> 5, lane = tid & 31;
    __shared__ float qs[Hsz][Ssz][33], ks[Hsz][Ssz][33], vs[Hsz][Ssz][33];
    __shared__ float sc[Hsz][Ssz][Ssz + 1];
    __shared__ int exS[Ssz], useS[Ssz], idxS[Ssz], midS[Ssz];

    if (b == 0 && tid == 0) g_acc = 0.0f;
    if (tid < Ssz) {
        int r = b * Ssz + tid;
        exS[tid]  = (mask[r] > 0);
        useS[tid] = g_use[r];
        idxS[tid] = g_r2c[r];
        midS[tid] = g_use[r] ? g_m2c[r] : 0;
    }
    __syncthreads();
    if (!g_any[b]) return;

    #pragma unroll
    for (int s = 0; s < Ssz; s++) {
        size_t base = (size_t)idxS[s] * REDsz + h * DHsz + lane;
        ks[h][s][lane] = g_kc[base];
        vs[h][s][lane] = g_vc[base];
        if (useS[s]) qs[h][s][lane] = g_qc[base];
    }
    __syncwarp();

    for (int idx = lane; idx < Ssz * Ssz; idx += 32) {
        int i = idx / Ssz, j = idx - i * Ssz;
        if (!useS[i]) continue;
        float dot = 0.0f;
        #pragma unroll
        for (int d = 0; d < 32; d++) dot += qs[h][i][d] * ks[h][j][d];
        sc[h][i][j] = exS[j] ? dot * 0.17677669529663687f : -1e9f;
    }
    __syncwarp();

    if (lane < Ssz && useS[lane]) {
        int i = lane;
        float m = -1e30f;
        #pragma unroll
        for (int j = 0; j < Ssz; j++) m = fmaxf(m, sc[h][i][j]);
        float sum = 0.0f;
        #pragma unroll
        for (int j = 0; j < Ssz; j++) { float e = expf(sc[h][i][j] - m); sc[h][i][j] = e; sum += e; }
        float inv = 1.0f / sum;
        #pragma unroll
        for (int j = 0; j < Ssz; j++) sc[h][i][j] *= inv;
    }
    __syncwarp();

    #pragma unroll
    for (int i = 0; i < Ssz; i++) {
        if (!useS[i]) continue;
        float s = 0.0f;
        #pragma unroll
        for (int j = 0; j < Ssz; j++) s += sc[h][i][j] * vs[h][j][lane];
        g_ctxc[(size_t)midS[i] * REDsz + h * DHsz + lane] = __float2half_rn(s);
    }
}

// ---------------- merged orthogonality loss + logits (R14) ----------------
__global__ void losslogit_k(const float* __restrict__ Wp, const float* __restrict__ bp,
                            float* __restrict__ out, int loff)
{
    int b = blockIdx.x, tid = threadIdx.x;
    __shared__ float X[Ssz][REDsz + 1];
    __shared__ float inv[Ssz];
    __shared__ float mean[REDsz];
    __shared__ const float* srcS[Ssz];
    if (tid < Ssz) {
        int r = b * Ssz + tid;
        srcS[tid] = g_use[r] ? &g_updc[(size_t)g_m2c[r] * 256]
                             : &g_redc[(size_t)g_r2c[r] * 256];
    }
    __syncthreads();
    for (int idx = tid; idx < Ssz * REDsz; idx += 256) {
        int s = idx >> 8, d = idx & 255;
        X[s][d] = srcS[s][d];
    }
    __syncthreads();
    int w = tid >> 5, lane = tid & 31;
    for (int r = w; r < Ssz; r += 8) {
        float s = 0.0f;
        for (int d = lane; d < 256; d += 32) s += X[r][d] * X[r][d];
        for (int o = 16; o > 0; o >>= 1) s += __shfl_down_sync(0xffffffffu, s, o);
        if (lane == 0) inv[r] = 1.0f / fmaxf(sqrtf(s), 1e-8f);
    }
    {
        float s = 0.0f;
        #pragma unroll
        for (int ss = 0; ss < Ssz; ss++) s += X[ss][tid];
        mean[tid] = s * (1.0f / (float)Ssz);
    }
    __syncthreads();
    float part = 0.0f;
    if (tid < (Ssz * (Ssz - 1)) / 2) {
        int p = tid, i = 0;
        while (p >= Ssz - 1 - i) { p -= Ssz - 1 - i; i++; }
        int j = i + 1 + p;
        float dot = 0.0f;
        for (int d = 0; d < 256; d++) dot += X[i][d] * X[j][d];
        float gv = fabsf(dot * inv[i] * inv[j]);
        part = fmaxf(gv - 0.1f, 0.0f) * 2.0f;
    }
    __shared__ float red[256];
    red[tid] = part; __syncthreads();
    for (int s = 128; s > 0; s >>= 1) { if (tid < s) red[tid] += red[tid + s]; __syncthreads(); }
    if (tid == 0) atomicAdd(&g_acc, red[0]);
    if (tid < NLAB) {
        float a = bp[tid];
        const float* wr = Wp + tid * REDsz;
        for (int d = 0; d < REDsz; d++) a += mean[d] * wr[d];
        out[loff + b * NLAB + tid] = a;
    }
}

__global__ void fin_k(float* out, int writeloss)
{
    if (writeloss)
        out[0] = g_acc * (1.0f / ((float)Bsz * Ssz * (Ssz - 1)));
}

// ---------------- launch ----------------
extern "C" void kernel_launch(void* const* d_in, const int* in_sizes, int n_in,
                              void* d_out, int out_size)
{
    const float* cls  = (const float*)d_in[0];
    const int*   mask = (const int*)  d_in[1];
    const float* miss = (const float*)d_in[2];
    const float* W1 = (const float*)d_in[3];  const float* b1 = (const float*)d_in[4];
    const float* W2 = (const float*)d_in[5];  const float* b2 = (const float*)d_in[6];
    const float* lg = (const float*)d_in[7];  const float* lb = (const float*)d_in[8];
    const float* Wq = (const float*)d_in[9];  const float* bq = (const float*)d_in[10];
    const float* Wk = (const float*)d_in[11]; const float* bk = (const float*)d_in[12];
    const float* Wv = (const float*)d_in[13]; const float* bv = (const float*)d_in[14];
    const float* Wo = (const float*)d_in[15]; const float* bo = (const float*)d_in[16];
    const float* Wp = (const float*)d_in[17]; const float* bp = (const float*)d_in[18];
    float* out = (float*)d_out;

    int loff = out_size - Bsz * NLAB;
    if (loff < 0) loff = 0;

    __half *ac, *h1c, *redch, *ctxc, *wh;
    float *qc, *kc, *vc, *updc;
    cudaGetSymbolAddress((void**)&ac,    g_ac);
    cudaGetSymbolAddress((void**)&h1c,   g_h1c);
    cudaGetSymbolAddress((void**)&redch, g_redch);
    cudaGetSymbolAddress((void**)&qc,    g_qc);
    cudaGetSymbolAddress((void**)&kc,    g_kc);
    cudaGetSymbolAddress((void**)&vc,    g_vc);
    cudaGetSymbolAddress((void**)&ctxc,  g_ctxc);
    cudaGetSymbolAddress((void**)&updc,  g_updc);
    cudaGetSymbolAddress((void**)&wh,    g_wh);

    cudaFuncSetAttribute(mmagemm_k<1,0,1,1>, cudaFuncAttributeMaxDynamicSharedMemorySize, SMEM_DYN);
    cudaFuncSetAttribute(mmagemm_k<0,3,0,1>, cudaFuncAttributeMaxDynamicSharedMemorySize, SMEM_DYN);
    cudaFuncSetAttribute(mmagemm_k<0,0,0,2>, cudaFuncAttributeMaxDynamicSharedMemorySize, SMEM_DYN);
    cudaFuncSetAttribute(gemm2ln_k, cudaFuncAttributeMaxDynamicSharedMemorySize, SMEM2);

    dim3 blk(256);
    // 0) prep
    prep_k<<<(Bsz + 255) / 256, 256>>>(mask);
    assign_k<<<(Mrows + 255) / 256, 256>>>(mask);
    acopy_k<<<(((Mrows + Ssz) * (Esz / 8)) + 255) / 256, 256>>>(cls, miss, mask);
    wprep_k<<<(WTOT + 255) / 256, 256>>>(W1, W2, Wq, Wk, Wv, Wo);
    // 1) GEMM1 + GELU (compacted) -> fp16 h1c
    mmagemm_k<1,0,1,1><<<dim3(3, MCtiles), blk, SMEM_DYN>>>(
        ac, wh + OFF_W1, nullptr, nullptr, b1, nullptr, nullptr,
        h1c, nullptr, nullptr, 384, 768);
    // 2+3) fused GEMM2 + GELU + LayerNorm -> redc + redch
    gemm2ln_k<<<dim3(1, 2 * MCtiles), blk, SMEM2>>>(
        h1c, wh + OFF_W2, b2, lg, lb);
    // 4) fused QKV (compacted; q-branch only tile 0)
    mmagemm_k<0,3,0,1><<<dim3(6, MCtiles), blk, SMEM_DYN>>>(
        redch, wh + OFF_WQ, wh + OFF_WK, wh + OFF_WV, bq, bk, bv,
        qc, kc, vc, 256, 256);
    // 5) attention (only use-rows)
    attn_k<<<Bsz, 256>>>(mask);
    // 6) Wo projection over missing rows only -> updc
    mmagemm_k<0,0,0,2><<<dim3(2, Mrows/128), blk, SMEM_DYN>>>(
        ctxc, wh + OFF_WO, nullptr, nullptr, bo, nullptr, nullptr,
        updc, nullptr, nullptr, 256, 256);
    // 7) merged orthogonality loss + logits
    losslogit_k<<<Bsz, 256>>>(Wp, bp, out, loff);
    // 8) finalize loss scalar
    fin_k<<<1, 1>>>(out, loff >= 1 ? 1 : 0);
}